// round 5
// baseline (speedup 1.0000x reference)
#include <cuda_runtime.h>
#include <cstdint>

#define NBLK   128
#define NTHR   256
#define SEQ    1024
#define TLEN   256
#define HID    512
#define NSTEPS (SEQ + TLEN)
#define BTILE  64      // batches per CTA
#define HTILE  16      // hidden units per CTA (=> 64 gate cols)
#define NC     64      // gate columns per CTA
#define WS     516     // W_s row stride (512 + 4 pad)
#define AS2    68      // A chunk row stride (64 + 4 pad)
#define GS     68      // gates_s row stride
#define CF     (BTILE * AS2)   // floats per A chunk buffer

__device__ unsigned g_bar_count;
__device__ unsigned g_bar_gen;
__device__ float    g_h[2][256][HID];   // ping-pong hidden state

__device__ __forceinline__ float tf32r(float x) {
    unsigned t;
    asm("cvt.rna.tf32.f32 %0, %1;" : "=r"(t) : "f"(x));
    return __uint_as_float(t);
}
__device__ __forceinline__ float tanh_fast(float x) {
    float y;
    asm("tanh.approx.f32 %0, %1;" : "=f"(y) : "f"(x));
    return y;
}
__device__ __forceinline__ float sigm(float x) {
    return fmaf(tanh_fast(0.5f * x), 0.5f, 0.5f);
}

// Device-wide barrier. 128 CTAs, 1/SM => co-resident, spin is safe.
// acq_rel RMW arrival; ld.acquire spin; release gen-flip.
__device__ __forceinline__ void gridbar() {
    __syncthreads();
    if (threadIdx.x == 0) {
        unsigned target = *(volatile unsigned*)&g_bar_gen;
        unsigned arr;
        asm volatile("atom.acq_rel.gpu.global.add.u32 %0, [%1], 1;"
                     : "=r"(arr) : "l"(&g_bar_count) : "memory");
        if (arr == NBLK - 1) {
            asm volatile("st.relaxed.gpu.global.u32 [%0], %1;"
                         :: "l"(&g_bar_count), "r"(0u) : "memory");
            asm volatile("red.release.gpu.global.add.u32 [%0], %1;"
                         :: "l"(&g_bar_gen), "r"(1u) : "memory");
        } else {
            unsigned g;
            do {
                __nanosleep(20);
                asm volatile("ld.acquire.gpu.global.u32 %0, [%1];"
                             : "=r"(g) : "l"(&g_bar_gen) : "memory");
            } while (g == target);
        }
    }
    __syncthreads();
}

__device__ __forceinline__ void load_w(const float* __restrict__ Whh,
                                       const float* __restrict__ bih,
                                       const float* __restrict__ bhh,
                                       const float* __restrict__ Wih,
                                       float* W_s, float* bias_s, float* wih_s,
                                       int h_base, int tid) {
    // SMEM gate-col n = g*16 + jj  <->  global gate row g*512 + h_base + jj
    for (int idx = tid; idx < NC * HID; idx += NTHR) {
        int n = idx >> 9;
        int k = idx & (HID - 1);
        int grow = (n >> 4) * HID + h_base + (n & 15);
        W_s[n * WS + k] = tf32r(Whh[grow * HID + k]);
    }
    if (tid < NC) {
        int grow = (tid >> 4) * HID + h_base + (tid & 15);
        bias_s[tid] = bih[grow] + bhh[grow];
        wih_s[tid]  = Wih[grow];
    }
}

// One 64-wide K chunk (64 rows x 64 cols fp32), loaded by 128 threads of a group.
__device__ __forceinline__ void copy_chunk64(const float* __restrict__ hsrc,
                                             float* buf, int kbase, int b_base, int gtid) {
    unsigned sbase = (unsigned)__cvta_generic_to_shared(buf);
    #pragma unroll
    for (int it = 0; it < 8; ++it) {
        int idx = it * 128 + gtid;          // 0..1023 float4
        int row = idx >> 4;
        int c4  = (idx & 15) * 4;
        const float* g = hsrc + (b_base + row) * HID + kbase + c4;
        unsigned s = sbase + (unsigned)(row * AS2 + c4) * 4u;
        asm volatile("cp.async.cg.shared.global [%0], [%1], 16;" :: "r"(s), "l"(g));
    }
}

#define MMA_TF32(C, A, B)                                                   \
    asm volatile(                                                           \
        "mma.sync.aligned.m16n8k8.row.col.f32.tf32.tf32.f32 "               \
        "{%0,%1,%2,%3}, {%4,%5,%6,%7}, {%8,%9}, {%0,%1,%2,%3};"             \
        : "+f"(C[0]), "+f"(C[1]), "+f"(C[2]), "+f"(C[3])                    \
        : "r"(A[0]), "r"(A[1]), "r"(A[2]), "r"(A[3]), "r"(B[0]), "r"(B[1]))

#define BARG() asm volatile("bar.sync %0, 128;" :: "r"(1 + kg) : "memory")

__global__ void __launch_bounds__(NTHR, 1)
lstm_seq2seq_kernel(const float* __restrict__ inputs,
                    const float* __restrict__ eWih, const float* __restrict__ eWhh,
                    const float* __restrict__ ebih, const float* __restrict__ ebhh,
                    const float* __restrict__ dWih, const float* __restrict__ dWhh,
                    const float* __restrict__ dbih, const float* __restrict__ dbhh,
                    const float* __restrict__ linW, const float* __restrict__ linb,
                    float* __restrict__ out) {
    extern __shared__ float sm[];
    float* W_s    = sm;                    // 64 x 516
    float* A_s    = W_s + NC * WS;         // 4 x 64 x 68 (2 groups x 2 buffers)
    float* G_s    = A_s + 4 * CF;          // 64 x 68
    float* bias_s = G_s + BTILE * GS;      // 64
    float* wih_s  = bias_s + NC;           // 64
    float* x_s    = wih_s + NC;            // 64

    const int tid    = threadIdx.x;
    const int bx     = blockIdx.x;
    const int b_base = (bx & 3) * BTILE;   // 4 batch tiles
    const int htile  = bx >> 2;            // 32 hidden tiles
    const int h_base = htile * HTILE;
    const int lane   = tid & 31;
    const int warp   = tid >> 5;
    const int kg     = warp >> 2;          // K-group: warps 0-3 -> k[0,256), 4-7 -> k[256,512)
    const int gtid   = tid & 127;
    const int wm     = (warp >> 1) & 1;    // 2x2 warp grid inside group, warp tile 32x32
    const int wn     = warp & 1;
    const int jj     = tid & 15;
    const int bq     = tid >> 4;           // 0..15

    float* mybuf0 = A_s + (kg * 2) * CF;
    float* mybuf1 = mybuf0 + CF;
    const int kg_base = kg * 256;

    // Init: zero g_h[0] and d_out (poisoned by harness)
    {
        float* h0 = &g_h[0][0][0];
        for (int i = tid; i < 1024; i += NTHR) h0[bx * 1024 + i] = 0.0f;
        for (int i = tid; i < 512;  i += NTHR) out[bx * 512 + i] = 0.0f;
    }
    load_w(eWhh, ebih, ebhh, eWih, W_s, bias_s, wih_s, h_base, tid);

    const float lw  = linW[h_base + jj];
    const float lb0 = linb[0];
    float creg[4];                         // cell state in registers (4 cells/thread)
    #pragma unroll
    for (int i = 0; i < 4; ++i) creg[i] = 0.0f;

    gridbar();

    for (int s = 0; s < NSTEPS; ++s) {
        const int  cur = s & 1;
        const int  nxt = cur ^ 1;
        const bool dec = (s >= SEQ);

        if (s == SEQ) {                    // switch to decoder weights
            load_w(dWhh, dbih, dbhh, dWih, W_s, bias_s, wih_s, h_base, tid);
            __syncthreads();
        }

        if (tid < BTILE) {
            float xv;
            if (!dec)          xv = inputs[(b_base + tid) * SEQ + s];
            else if (s == SEQ) xv = inputs[(b_base + tid) * SEQ + (SEQ - 1)];
            else               xv = __ldcg(&out[(b_base + tid) * TLEN + (s - SEQ - 1)]);
            x_s[tid] = xv;
        }

        float C[2][4][4];
        #pragma unroll
        for (int t = 0; t < 2; ++t)
            #pragma unroll
            for (int u = 0; u < 4; ++u)
                #pragma unroll
                for (int r = 0; r < 4; ++r) C[t][u][r] = 0.0f;

        const float* hsrc = &g_h[cur][0][0];
        copy_chunk64(hsrc, mybuf0, kg_base, b_base, gtid);
        asm volatile("cp.async.commit_group;");

        #pragma unroll 1
        for (int ch = 0; ch < 4; ++ch) {
            if (ch < 3) {
                copy_chunk64(hsrc, ((ch + 1) & 1) ? mybuf1 : mybuf0,
                             kg_base + (ch + 1) * 64, b_base, gtid);
                asm volatile("cp.async.commit_group;");
                asm volatile("cp.async.wait_group 1;");
            } else {
                asm volatile("cp.async.wait_group 0;");
            }
            BARG();
            const float* Ab = (ch & 1) ? mybuf1 : mybuf0;
            const int    kb = kg_base + ch * 64;
            #pragma unroll
            for (int kk = 0; kk < 64; kk += 8) {
                unsigned a[2][4], b[4][2];
                const int ar = wm * 32 + (lane >> 2);
                const int ac = kk + (lane & 3);
                #pragma unroll
                for (int t = 0; t < 2; ++t) {
                    const float* ap = Ab + (ar + t * 16) * AS2 + ac;
                    a[t][0] = __float_as_uint(ap[0]);
                    a[t][1] = __float_as_uint(ap[8 * AS2]);
                    a[t][2] = __float_as_uint(ap[4]);
                    a[t][3] = __float_as_uint(ap[8 * AS2 + 4]);
                }
                const int bc = kb + kk + (lane & 3);
                #pragma unroll
                for (int u = 0; u < 4; ++u) {
                    const float* bp = W_s + (wn * 32 + u * 8 + (lane >> 2)) * WS + bc;
                    b[u][0] = __float_as_uint(bp[0]);
                    b[u][1] = __float_as_uint(bp[4]);
                }
                #pragma unroll
                for (int t = 0; t < 2; ++t)
                    #pragma unroll
                    for (int u = 0; u < 4; ++u)
                        MMA_TF32(C[t][u], a[t], b[u]);
            }
            BARG();
        }

        // Merge partial sums: group0 writes G, group1 adds.
        __syncthreads();
        if (kg == 0) {
            #pragma unroll
            for (int t = 0; t < 2; ++t) {
                const int r = wm * 32 + t * 16 + (lane >> 2);
                #pragma unroll
                for (int u = 0; u < 4; ++u) {
                    const int cc = wn * 32 + u * 8 + (lane & 3) * 2;
                    *(float2*)&G_s[r * GS + cc]       = make_float2(C[t][u][0], C[t][u][1]);
                    *(float2*)&G_s[(r + 8) * GS + cc] = make_float2(C[t][u][2], C[t][u][3]);
                }
            }
        }
        __syncthreads();
        if (kg == 1) {
            #pragma unroll
            for (int t = 0; t < 2; ++t) {
                const int r = wm * 32 + t * 16 + (lane >> 2);
                #pragma unroll
                for (int u = 0; u < 4; ++u) {
                    const int cc = wn * 32 + u * 8 + (lane & 3) * 2;
                    float2* p0 = (float2*)&G_s[r * GS + cc];
                    float2* p1 = (float2*)&G_s[(r + 8) * GS + cc];
                    float2 v0 = *p0, v1 = *p1;
                    v0.x += C[t][u][0]; v0.y += C[t][u][1];
                    v1.x += C[t][u][2]; v1.y += C[t][u][3];
                    *p0 = v0; *p1 = v1;
                }
            }
        }
        __syncthreads();

        // Epilogue: 4 cells per thread; cell (b, jj), c in registers
        #pragma unroll
        for (int ci = 0; ci < 4; ++ci) {
            const int   b  = bq + ci * 16;
            const float xv = x_s[b];
            const float* gr = G_s + b * GS;
            const float gi = gr[jj]      + bias_s[jj]      + xv * wih_s[jj];
            const float gf = gr[16 + jj] + bias_s[16 + jj] + xv * wih_s[16 + jj];
            const float gg = gr[32 + jj] + bias_s[32 + jj] + xv * wih_s[32 + jj];
            const float go = gr[48 + jj] + bias_s[48 + jj] + xv * wih_s[48 + jj];
            const float cn = sigm(gf) * creg[ci] + sigm(gi) * tanh_fast(gg);
            creg[ci] = cn;
            float h = sigm(go) * tanh_fast(cn);
            h = tf32r(h);                              // producer-side tf32 rounding
            g_h[nxt][b_base + b][h_base + jj] = h;
            if (dec) {
                float p = h * lw;
                #pragma unroll
                for (int off = 8; off; off >>= 1)
                    p += __shfl_xor_sync(0xffffffffu, p, off);
                if (jj == 0) {
                    if (htile == 0) p += lb0;
                    atomicAdd(&out[(b_base + b) * TLEN + (s - SEQ)], p);
                }
            }
        }
        gridbar();
    }
}

extern "C" void kernel_launch(void* const* d_in, const int* in_sizes, int n_in,
                              void* d_out, int out_size) {
    const float* inputs = (const float*)d_in[0];
    const float* eWih   = (const float*)d_in[1];
    const float* eWhh   = (const float*)d_in[2];
    const float* ebih   = (const float*)d_in[3];
    const float* ebhh   = (const float*)d_in[4];
    const float* dWih   = (const float*)d_in[5];
    const float* dWhh   = (const float*)d_in[6];
    const float* dbih   = (const float*)d_in[7];
    const float* dbhh   = (const float*)d_in[8];
    const float* linW   = (const float*)d_in[9];
    const float* linb   = (const float*)d_in[10];
    float* out = (float*)d_out;

    const int smem = (NC * WS + 4 * CF + BTILE * GS + 3 * NC) * sizeof(float); // 219904 B
    cudaFuncSetAttribute(lstm_seq2seq_kernel,
                         cudaFuncAttributeMaxDynamicSharedMemorySize, smem);
    lstm_seq2seq_kernel<<<NBLK, NTHR, smem>>>(inputs, eWih, eWhh, ebih, ebhh,
                                              dWih, dWhh, dbih, dbhh, linW, linb, out);
}

// round 6
// speedup vs baseline: 1.8034x; 1.8034x over previous
#include <cuda_runtime.h>
#include <cuda_bf16.h>
#include <cstdint>

#define NBLK   128
#define NTHR   256
#define SEQ    1024
#define TLEN   256
#define HID    512
#define NSTEPS (SEQ + TLEN)
#define BTILE  64      // batches per CTA
#define NC     64      // gate columns per CTA (4 gates x 16 hidden)
#define PITCH  520     // bf16 elems per SMEM row: 1040B, %128 = 16 -> LDSM conflict-free
#define GS     68      // gates_s row stride (floats)

__device__ unsigned g_bar_count;
__device__ unsigned g_bar_gen;
__device__ __nv_bfloat16 g_h[2][256][HID];   // ping-pong hidden state (bf16)

__device__ __forceinline__ float tanh_fast(float x) {
    float y;
    asm("tanh.approx.f32 %0, %1;" : "=f"(y) : "f"(x));
    return y;
}
__device__ __forceinline__ float sigm(float x) {
    return fmaf(tanh_fast(0.5f * x), 0.5f, 0.5f);
}

// Device-wide barrier. 128 CTAs, 1/SM => co-resident, spin safe.
__device__ __forceinline__ void gridbar() {
    __syncthreads();
    if (threadIdx.x == 0) {
        unsigned target = *(volatile unsigned*)&g_bar_gen;
        unsigned arr;
        asm volatile("atom.acq_rel.gpu.global.add.u32 %0, [%1], 1;"
                     : "=r"(arr) : "l"(&g_bar_count) : "memory");
        if (arr == NBLK - 1) {
            asm volatile("st.relaxed.gpu.global.u32 [%0], %1;"
                         :: "l"(&g_bar_count), "r"(0u) : "memory");
            asm volatile("red.release.gpu.global.add.u32 [%0], %1;"
                         :: "l"(&g_bar_gen), "r"(1u) : "memory");
        } else {
            unsigned g;
            do {
                __nanosleep(20);
                asm volatile("ld.acquire.gpu.global.u32 %0, [%1];"
                             : "=r"(g) : "l"(&g_bar_gen) : "memory");
            } while (g == target);
        }
    }
    __syncthreads();
}

__device__ __forceinline__ void load_w(const float* __restrict__ Whh,
                                       const float* __restrict__ bih,
                                       const float* __restrict__ bhh,
                                       const float* __restrict__ Wih,
                                       __nv_bfloat16* W_s, float* bias_s, float* wih_s,
                                       int h_base, int tid) {
    // SMEM gate-col n = g*16 + jj  <->  global gate row g*512 + h_base + jj
    for (int idx = tid; idx < NC * HID; idx += NTHR) {
        int n = idx >> 9;
        int k = idx & (HID - 1);
        int grow = (n >> 4) * HID + h_base + (n & 15);
        W_s[n * PITCH + k] = __float2bfloat16_rn(Whh[grow * HID + k]);
    }
    if (tid < NC) {
        int grow = (tid >> 4) * HID + h_base + (tid & 15);
        bias_s[tid] = bih[grow] + bhh[grow];
        wih_s[tid]  = Wih[grow];
    }
}

#define LDSM_X4(R, addr)                                                      \
    asm volatile("ldmatrix.sync.aligned.m8n8.x4.shared.b16 {%0,%1,%2,%3}, [%4];" \
                 : "=r"((R)[0]), "=r"((R)[1]), "=r"((R)[2]), "=r"((R)[3])     \
                 : "r"(addr))

#define MMA_BF16(C, A, B0, B1)                                                \
    asm volatile(                                                             \
        "mma.sync.aligned.m16n8k16.row.col.f32.bf16.bf16.f32 "                \
        "{%0,%1,%2,%3}, {%4,%5,%6,%7}, {%8,%9}, {%0,%1,%2,%3};"               \
        : "+f"((C)[0]), "+f"((C)[1]), "+f"((C)[2]), "+f"((C)[3])              \
        : "r"((A)[0]), "r"((A)[1]), "r"((A)[2]), "r"((A)[3]), "r"(B0), "r"(B1))

__global__ void __launch_bounds__(NTHR, 1)
lstm_seq2seq_kernel(const float* __restrict__ inputs,
                    const float* __restrict__ eWih, const float* __restrict__ eWhh,
                    const float* __restrict__ ebih, const float* __restrict__ ebhh,
                    const float* __restrict__ dWih, const float* __restrict__ dWhh,
                    const float* __restrict__ dbih, const float* __restrict__ dbhh,
                    const float* __restrict__ linW, const float* __restrict__ linb,
                    float* __restrict__ out) {
    extern __shared__ char smraw[];
    __nv_bfloat16* W_s = (__nv_bfloat16*)smraw;        // 64 x 520 bf16
    __nv_bfloat16* A_s = W_s + NC * PITCH;             // 64 x 520 bf16 (full K)
    float* G_s    = (float*)(A_s + BTILE * PITCH);     // 64 x 68 f32
    float* bias_s = G_s + BTILE * GS;                  // 64
    float* wih_s  = bias_s + NC;                       // 64
    float* x_s    = wih_s + NC;                        // 64

    const int tid    = threadIdx.x;
    const int bx     = blockIdx.x;
    const int b_base = (bx & 3) * BTILE;   // 4 batch tiles
    const int htile  = bx >> 2;            // 32 hidden tiles
    const int h_base = htile * 16;
    const int lane   = tid & 31;
    const int warp   = tid >> 5;
    const int wm     = warp >> 2;          // 2x4 warp grid, warp tile 32(m) x 16(n)
    const int wn     = warp & 3;
    const int jj     = tid & 15;
    const int bq     = tid >> 4;           // 0..15

    // Precompute ldmatrix lane addresses (byte offsets into SMEM, u32 space)
    const unsigned a_u32 = (unsigned)__cvta_generic_to_shared(A_s);
    const unsigned w_u32 = (unsigned)__cvta_generic_to_shared(W_s);
    const int lg = lane >> 3, lr = lane & 7;
    // A tiles t=0,1: rows m = wm*32 + t*16 + (lg&1)*8 + lr, col group (lg>>1)*8
    unsigned aAddr[2];
    #pragma unroll
    for (int t = 0; t < 2; ++t) {
        int row = wm * 32 + t * 16 + (lg & 1) * 8 + lr;
        int cg  = (lg >> 1) * 8;
        aAddr[t] = a_u32 + (unsigned)(row * PITCH + cg) * 2u;
    }
    // B tile: n rows wn*16 + (lg>>1)*8 + lr, k group (lg&1)*8
    unsigned bAddr;
    {
        int rown = wn * 16 + (lg >> 1) * 8 + lr;
        int kg   = (lg & 1) * 8;
        bAddr = w_u32 + (unsigned)(rown * PITCH + kg) * 2u;
    }

    // Init: zero g_h[0] and d_out (poisoned by harness)
    {
        unsigned* h0 = (unsigned*)&g_h[0][0][0];       // 65536 uints total
        for (int i = tid; i < 512; i += NTHR) h0[bx * 512 + i] = 0u;
        for (int i = tid; i < 512; i += NTHR) out[bx * 512 + i] = 0.0f;
    }
    load_w(eWhh, ebih, ebhh, eWih, W_s, bias_s, wih_s, h_base, tid);

    const float lw  = linW[h_base + jj];
    const float lb0 = linb[0];
    float creg[4];                         // cell state in registers
    #pragma unroll
    for (int i = 0; i < 4; ++i) creg[i] = 0.0f;

    gridbar();

    for (int s = 0; s < NSTEPS; ++s) {
        const int  cur = s & 1;
        const int  nxt = cur ^ 1;
        const bool dec = (s >= SEQ);

        if (s == SEQ) {                    // switch to decoder weights
            load_w(dWhh, dbih, dbhh, dWih, W_s, bias_s, wih_s, h_base, tid);
            __syncthreads();
        }

        // Issue all 4 K-chunk loads (h tile, bf16) as separate commit groups
        const __nv_bfloat16* hsrc = &g_h[cur][0][0];
        #pragma unroll
        for (int ch = 0; ch < 4; ++ch) {
            #pragma unroll
            for (int it = 0; it < 4; ++it) {
                int idx = it * NTHR + tid;          // 0..1023 (64 rows x 16 segs)
                int row = idx >> 4;
                int k   = ch * 128 + (idx & 15) * 8;
                const __nv_bfloat16* g = hsrc + (b_base + row) * HID + k;
                unsigned sdst = a_u32 + (unsigned)(row * PITCH + k) * 2u;
                asm volatile("cp.async.cg.shared.global [%0], [%1], 16;"
                             :: "r"(sdst), "l"(g));
            }
            asm volatile("cp.async.commit_group;");
        }

        if (tid < BTILE) {
            float xv;
            if (!dec)          xv = inputs[(b_base + tid) * SEQ + s];
            else if (s == SEQ) xv = inputs[(b_base + tid) * SEQ + (SEQ - 1)];
            else               xv = __ldcg(&out[(b_base + tid) * TLEN + (s - SEQ - 1)]);
            x_s[tid] = xv;
        }

        float C[2][2][4];
        #pragma unroll
        for (int t = 0; t < 2; ++t)
            #pragma unroll
            for (int u = 0; u < 2; ++u)
                #pragma unroll
                for (int r = 0; r < 4; ++r) C[t][u][r] = 0.0f;

        #pragma unroll 1
        for (int ch = 0; ch < 4; ++ch) {
            switch (ch) {  // wait until chunk ch has landed
                case 0: asm volatile("cp.async.wait_group 3;"); break;
                case 1: asm volatile("cp.async.wait_group 2;"); break;
                case 2: asm volatile("cp.async.wait_group 1;"); break;
                default: asm volatile("cp.async.wait_group 0;"); break;
            }
            __syncthreads();
            #pragma unroll
            for (int ki = 0; ki < 8; ++ki) {
                const unsigned kkb = (unsigned)(ch * 128 + ki * 16) * 2u;
                unsigned a0[4], a1[4], bf[4];
                LDSM_X4(a0, aAddr[0] + kkb);
                LDSM_X4(a1, aAddr[1] + kkb);
                LDSM_X4(bf, bAddr + kkb);
                MMA_BF16(C[0][0], a0, bf[0], bf[1]);
                MMA_BF16(C[0][1], a0, bf[2], bf[3]);
                MMA_BF16(C[1][0], a1, bf[0], bf[1]);
                MMA_BF16(C[1][1], a1, bf[2], bf[3]);
            }
        }

        // C frags -> gates SMEM (full-K per warp: direct store, no merge)
        __syncthreads();   // A_s reads done before G_s writes alias epilogue timing
        #pragma unroll
        for (int t = 0; t < 2; ++t) {
            const int r = wm * 32 + t * 16 + (lane >> 2);
            #pragma unroll
            for (int u = 0; u < 2; ++u) {
                const int cc = wn * 16 + u * 8 + (lane & 3) * 2;
                *(float2*)&G_s[r * GS + cc]       = make_float2(C[t][u][0], C[t][u][1]);
                *(float2*)&G_s[(r + 8) * GS + cc] = make_float2(C[t][u][2], C[t][u][3]);
            }
        }
        __syncthreads();

        // Epilogue: 4 cells per thread; cell (b, jj), c in registers
        #pragma unroll
        for (int ci = 0; ci < 4; ++ci) {
            const int   b  = bq + ci * 16;
            const float xv = x_s[b];
            const float* gr = G_s + b * GS;
            const float gi = gr[jj]      + bias_s[jj]      + xv * wih_s[jj];
            const float gf = gr[16 + jj] + bias_s[16 + jj] + xv * wih_s[16 + jj];
            const float gg = gr[32 + jj] + bias_s[32 + jj] + xv * wih_s[32 + jj];
            const float go = gr[48 + jj] + bias_s[48 + jj] + xv * wih_s[48 + jj];
            const float cn = sigm(gf) * creg[ci] + sigm(gi) * tanh_fast(gg);
            creg[ci] = cn;
            const float h = sigm(go) * tanh_fast(cn);
            g_h[nxt][b_base + b][h_base + jj] = __float2bfloat16_rn(h);
            if (dec) {
                float p = h * lw;
                #pragma unroll
                for (int off = 8; off; off >>= 1)
                    p += __shfl_xor_sync(0xffffffffu, p, off);
                if (jj == 0) {
                    if (htile == 0) p += lb0;
                    atomicAdd(&out[(b_base + b) * TLEN + (s - SEQ)], p);
                }
            }
        }
        gridbar();
    }
}

extern "C" void kernel_launch(void* const* d_in, const int* in_sizes, int n_in,
                              void* d_out, int out_size) {
    const float* inputs = (const float*)d_in[0];
    const float* eWih   = (const float*)d_in[1];
    const float* eWhh   = (const float*)d_in[2];
    const float* ebih   = (const float*)d_in[3];
    const float* ebhh   = (const float*)d_in[4];
    const float* dWih   = (const float*)d_in[5];
    const float* dWhh   = (const float*)d_in[6];
    const float* dbih   = (const float*)d_in[7];
    const float* dbhh   = (const float*)d_in[8];
    const float* linW   = (const float*)d_in[9];
    const float* linb   = (const float*)d_in[10];
    float* out = (float*)d_out;

    const int smem = (NC * PITCH + BTILE * PITCH) * 2          // bf16 W + A
                   + (BTILE * GS + 3 * NC) * 4;                // f32 G + bias/wih/x
    cudaFuncSetAttribute(lstm_seq2seq_kernel,
                         cudaFuncAttributeMaxDynamicSharedMemorySize, smem);
    lstm_seq2seq_kernel<<<NBLK, NTHR, smem>>>(inputs, eWih, eWhh, ebih, ebhh,
                                              dWih, dWhh, dbih, dbhh, linW, linb, out);
}

// round 8
// speedup vs baseline: 1.9534x; 1.0832x over previous
#include <cuda_runtime.h>
#include <cuda_bf16.h>
#include <cstdint>

#define NBLK   128
#define NTHR   256
#define SEQ    1024
#define TLEN   256
#define HID    512
#define NSTEPS (SEQ + TLEN)
#define BTILE  64      // batches per CTA
#define NC     64      // gate columns per CTA (4 gates x 16 hidden)
#define PITCH  520     // bf16 elems per SMEM row: 1040B, %128 = 16 -> LDSM conflict-free
#define GS     68      // gates_s row stride (floats)

__device__ unsigned g_bar_count;
__device__ unsigned g_bar_gen;
__device__ unsigned g_flags[4][32][32];      // [batch group][htile][128B pad]
__device__ __nv_bfloat16 g_h[2][256][HID];   // ping-pong hidden state (bf16)

__device__ __forceinline__ float tanh_fast(float x) {
    float y;
    asm("tanh.approx.f32 %0, %1;" : "=f"(y) : "f"(x));
    return y;
}
__device__ __forceinline__ float sigm(float x) {
    return fmaf(tanh_fast(0.5f * x), 0.5f, 0.5f);
}

// One-time device-wide barrier (init only). 128 CTAs, 1/SM => co-resident.
__device__ __forceinline__ void gridbar() {
    __syncthreads();
    if (threadIdx.x == 0) {
        unsigned target = *(volatile unsigned*)&g_bar_gen;
        unsigned arr;
        asm volatile("atom.acq_rel.gpu.global.add.u32 %0, [%1], 1;"
                     : "=r"(arr) : "l"(&g_bar_count) : "memory");
        if (arr == NBLK - 1) {
            asm volatile("st.relaxed.gpu.global.u32 [%0], %1;"
                         :: "l"(&g_bar_count), "r"(0u) : "memory");
            asm volatile("red.release.gpu.global.add.u32 [%0], %1;"
                         :: "l"(&g_bar_gen), "r"(1u) : "memory");
        } else {
            unsigned g;
            do {
                __nanosleep(20);
                asm volatile("ld.acquire.gpu.global.u32 %0, [%1];"
                             : "=r"(g) : "l"(&g_bar_gen) : "memory");
            } while (g == target);
        }
    }
    __syncthreads();
}

// Per-step barrier over the 32 CTAs of one batch group. No atomics:
// one release-store of (s+1) to this CTA's padded flag, 32 lanes poll peers.
__device__ __forceinline__ void groupbar(int bg, int my, unsigned target) {
    __syncthreads();
    if (threadIdx.x == 0)
        asm volatile("st.release.gpu.global.u32 [%0], %1;"
                     :: "l"(&g_flags[bg][my][0]), "r"(target) : "memory");
    if (threadIdx.x < 32) {
        const unsigned* fp = &g_flags[bg][threadIdx.x][0];
        unsigned v;
        while (true) {
            asm volatile("ld.acquire.gpu.global.u32 %0, [%1];"
                         : "=r"(v) : "l"(fp) : "memory");
            if (v >= target) break;
            __nanosleep(30);
        }
    }
    __syncthreads();
}

__device__ __forceinline__ void load_w(const float* __restrict__ Whh,
                                       const float* __restrict__ bih,
                                       const float* __restrict__ bhh,
                                       const float* __restrict__ Wih,
                                       __nv_bfloat16* W_s, float* bias_s, float* wih_s,
                                       int h_base, int tid) {
    // SMEM gate-col n = g*16 + jj  <->  global gate row g*512 + h_base + jj
    for (int idx = tid; idx < NC * HID; idx += NTHR) {
        int n = idx >> 9;
        int k = idx & (HID - 1);
        int grow = (n >> 4) * HID + h_base + (n & 15);
        W_s[n * PITCH + k] = __float2bfloat16_rn(Whh[grow * HID + k]);
    }
    if (tid < NC) {
        int grow = (tid >> 4) * HID + h_base + (tid & 15);
        bias_s[tid] = bih[grow] + bhh[grow];
        wih_s[tid]  = Wih[grow];
    }
}

#define LDSM_X4(R, addr)                                                      \
    asm volatile("ldmatrix.sync.aligned.m8n8.x4.shared.b16 {%0,%1,%2,%3}, [%4];" \
                 : "=r"((R)[0]), "=r"((R)[1]), "=r"((R)[2]), "=r"((R)[3])     \
                 : "r"(addr))

#define MMA_BF16(C, A, B0, B1)                                                \
    asm volatile(                                                             \
        "mma.sync.aligned.m16n8k16.row.col.f32.bf16.bf16.f32 "                \
        "{%0,%1,%2,%3}, {%4,%5,%6,%7}, {%8,%9}, {%0,%1,%2,%3};"               \
        : "+f"((C)[0]), "+f"((C)[1]), "+f"((C)[2]), "+f"((C)[3])              \
        : "r"((A)[0]), "r"((A)[1]), "r"((A)[2]), "r"((A)[3]), "r"(B0), "r"(B1))

__global__ void __launch_bounds__(NTHR, 1)
lstm_seq2seq_kernel(const float* __restrict__ inputs,
                    const float* __restrict__ eWih, const float* __restrict__ eWhh,
                    const float* __restrict__ ebih, const float* __restrict__ ebhh,
                    const float* __restrict__ dWih, const float* __restrict__ dWhh,
                    const float* __restrict__ dbih, const float* __restrict__ dbhh,
                    const float* __restrict__ linW, const float* __restrict__ linb,
                    float* __restrict__ out) {
    extern __shared__ char smraw[];
    __nv_bfloat16* W_s = (__nv_bfloat16*)smraw;        // 64 x 520 bf16
    __nv_bfloat16* A_s = W_s + NC * PITCH;             // 64 x 520 bf16 (full K)
    float* G_s    = (float*)(A_s + BTILE * PITCH);     // 64 x 68 f32
    float* bias_s = G_s + BTILE * GS;                  // 64
    float* wih_s  = bias_s + NC;                       // 64
    float* x_s    = wih_s + NC;                        // 64

    const int tid    = threadIdx.x;
    const int bx     = blockIdx.x;
    const int bg     = bx & 3;             // batch group (4 groups of 32 CTAs)
    const int b_base = bg * BTILE;
    const int htile  = bx >> 2;            // 32 hidden tiles
    const int h_base = htile * 16;
    const int lane   = tid & 31;
    const int warp   = tid >> 5;
    const int wm     = warp >> 2;          // 2x4 warp grid, warp tile 32(m) x 16(n)
    const int wn     = warp & 3;
    const int jj     = tid & 15;
    const int bq     = tid >> 4;           // 0..15

    // Precompute ldmatrix lane addresses
    const unsigned a_u32 = (unsigned)__cvta_generic_to_shared(A_s);
    const unsigned w_u32 = (unsigned)__cvta_generic_to_shared(W_s);
    const int lg = lane >> 3, lr = lane & 7;
    unsigned aAddr[2];
    #pragma unroll
    for (int t = 0; t < 2; ++t) {
        int row = wm * 32 + t * 16 + (lg & 1) * 8 + lr;
        int cg  = (lg >> 1) * 8;
        aAddr[t] = a_u32 + (unsigned)(row * PITCH + cg) * 2u;
    }
    unsigned bAddr;
    {
        int rown = wn * 16 + (lg >> 1) * 8 + lr;
        int kg   = (lg & 1) * 8;
        bAddr = w_u32 + (unsigned)(rown * PITCH + kg) * 2u;
    }

    // Init: zero g_h[0], d_out, and this CTA's flag (stale from prior launch)
    {
        unsigned* h0 = (unsigned*)&g_h[0][0][0];
        for (int i = tid; i < 512; i += NTHR) h0[bx * 512 + i] = 0u;
        for (int i = tid; i < 512; i += NTHR) out[bx * 512 + i] = 0.0f;
        if (tid == 0) g_flags[bg][htile][0] = 0u;
    }
    load_w(eWhh, ebih, ebhh, eWih, W_s, bias_s, wih_s, h_base, tid);

    const float lw  = linW[h_base + jj];
    const float lb0 = linb[0];
    float creg[4];
    #pragma unroll
    for (int i = 0; i < 4; ++i) creg[i] = 0.0f;

    gridbar();   // once: flags reset + h/out zero visible everywhere

    for (int s = 0; s < NSTEPS; ++s) {
        const int  cur = s & 1;
        const int  nxt = cur ^ 1;
        const bool dec = (s >= SEQ);

        if (s == SEQ)                      // switch to decoder weights
            load_w(dWhh, dbih, dbhh, dWih, W_s, bias_s, wih_s, h_base, tid);

        // Issue all 4 K-chunk loads (h tile, bf16) as separate commit groups
        const __nv_bfloat16* hsrc = &g_h[cur][0][0];
        #pragma unroll
        for (int ch = 0; ch < 4; ++ch) {
            #pragma unroll
            for (int it = 0; it < 4; ++it) {
                int idx = it * NTHR + tid;          // 0..1023 (64 rows x 16 segs)
                int row = idx >> 4;
                int k   = ch * 128 + (idx & 15) * 8;
                const __nv_bfloat16* g = hsrc + (b_base + row) * HID + k;
                unsigned sdst = a_u32 + (unsigned)(row * PITCH + k) * 2u;
                asm volatile("cp.async.cg.shared.global [%0], [%1], 16;"
                             :: "r"(sdst), "l"(g));
            }
            asm volatile("cp.async.commit_group;");
        }

        if (tid < BTILE) {
            float xv;
            if (!dec)          xv = inputs[(b_base + tid) * SEQ + s];
            else if (s == SEQ) xv = inputs[(b_base + tid) * SEQ + (SEQ - 1)];
            else               xv = __ldcg(&out[(b_base + tid) * TLEN + (s - SEQ - 1)]);
            x_s[tid] = xv;
        }

        float C[2][2][4];
        #pragma unroll
        for (int t = 0; t < 2; ++t)
            #pragma unroll
            for (int u = 0; u < 2; ++u)
                #pragma unroll
                for (int r = 0; r < 4; ++r) C[t][u][r] = 0.0f;

        #pragma unroll 1
        for (int ch = 0; ch < 4; ++ch) {
            switch (ch) {
                case 0: asm volatile("cp.async.wait_group 3;"); break;
                case 1: asm volatile("cp.async.wait_group 2;"); break;
                case 2: asm volatile("cp.async.wait_group 1;"); break;
                default: asm volatile("cp.async.wait_group 0;"); break;
            }
            __syncthreads();
            #pragma unroll
            for (int ki = 0; ki < 8; ++ki) {
                const unsigned kkb = (unsigned)(ch * 128 + ki * 16) * 2u;
                unsigned a0[4], a1[4], bf[4];
                LDSM_X4(a0, aAddr[0] + kkb);
                LDSM_X4(a1, aAddr[1] + kkb);
                LDSM_X4(bf, bAddr + kkb);
                MMA_BF16(C[0][0], a0, bf[0], bf[1]);
                MMA_BF16(C[0][1], a0, bf[2], bf[3]);
                MMA_BF16(C[1][0], a1, bf[0], bf[1]);
                MMA_BF16(C[1][1], a1, bf[2], bf[3]);
            }
        }

        // C frags -> gates SMEM (G_s disjoint from A_s: no pre-sync needed)
        #pragma unroll
        for (int t = 0; t < 2; ++t) {
            const int r = wm * 32 + t * 16 + (lane >> 2);
            #pragma unroll
            for (int u = 0; u < 2; ++u) {
                const int cc = wn * 16 + u * 8 + (lane & 3) * 2;
                *(float2*)&G_s[r * GS + cc]       = make_float2(C[t][u][0], C[t][u][1]);
                *(float2*)&G_s[(r + 8) * GS + cc] = make_float2(C[t][u][2], C[t][u][3]);
            }
        }
        __syncthreads();

        // Epilogue: 4 cells per thread; cell (b, jj), c in registers
        #pragma unroll
        for (int ci = 0; ci < 4; ++ci) {
            const int   b  = bq + ci * 16;
            const float xv = x_s[b];
            const float* gr = G_s + b * GS;
            const float gi = gr[jj]      + bias_s[jj]      + xv * wih_s[jj];
            const float gf = gr[16 + jj] + bias_s[16 + jj] + xv * wih_s[16 + jj];
            const float gg = gr[32 + jj] + bias_s[32 + jj] + xv * wih_s[32 + jj];
            const float go = gr[48 + jj] + bias_s[48 + jj] + xv * wih_s[48 + jj];
            const float cn = sigm(gf) * creg[ci] + sigm(gi) * tanh_fast(gg);
            creg[ci] = cn;
            const float h = sigm(go) * tanh_fast(cn);
            g_h[nxt][b_base + b][h_base + jj] = __float2bfloat16_rn(h);
            if (dec) {
                float p = h * lw;
                #pragma unroll
                for (int off = 8; off; off >>= 1)
                    p += __shfl_xor_sync(0xffffffffu, p, off);
                if (jj == 0) {
                    if (htile == 0) p += lb0;
                    atomicAdd(&out[(b_base + b) * TLEN + (s - SEQ)], p);
                }
            }
        }
        groupbar(bg, htile, (unsigned)(s + 1));
    }
}

extern "C" void kernel_launch(void* const* d_in, const int* in_sizes, int n_in,
                              void* d_out, int out_size) {
    const float* inputs = (const float*)d_in[0];
    const float* eWih   = (const float*)d_in[1];
    const float* eWhh   = (const float*)d_in[2];
    const float* ebih   = (const float*)d_in[3];
    const float* ebhh   = (const float*)d_in[4];
    const float* dWih   = (const float*)d_in[5];
    const float* dWhh   = (const float*)d_in[6];
    const float* dbih   = (const float*)d_in[7];
    const float* dbhh   = (const float*)d_in[8];
    const float* linW   = (const float*)d_in[9];
    const float* linb   = (const float*)d_in[10];
    float* out = (float*)d_out;

    const int smem = (NC * PITCH + BTILE * PITCH) * 2          // bf16 W + A
                   + (BTILE * GS + 3 * NC) * 4;                // f32 G + bias/wih/x
    cudaFuncSetAttribute(lstm_seq2seq_kernel,
                         cudaFuncAttributeMaxDynamicSharedMemorySize, smem);
    lstm_seq2seq_kernel<<<NBLK, NTHR, smem>>>(inputs, eWih, eWhh, ebih, ebhh,
                                              dWih, dWhh, dbih, dbhh, linW, linb, out);
}